// round 11
// baseline (speedup 1.0000x reference)
#include <cuda_runtime.h>
#include <cuda_bf16.h>
#include <cstdint>

#define B_   16
#define TQ_  128
#define TK_  256
#define DIN_ 64
#define H_   256
#define DV_  256
#define IT_  4
#define NEGV (-1000000.0f)

// Scratch (static device arrays: allocation-free). g_kT padded by 8 h-rows so
// the depth-2 prefetch can run past h=255 without wrap/guard arithmetic.
__device__ float g_q [B_ * TQ_ * H_];            // [B*Tq, H]
__device__ float g_kT[B_ * H_ * TK_ + 8 * TK_];  // [B, H, Tk] + pad

__device__ __forceinline__ float fast_tanh(float x) {
    float y;
    asm("tanh.approx.f32 %0, %1;" : "=f"(y) : "f"(x));
    return y;
}

// Pade(5,4) tanh: x(945+105t+t^2)/(945+420t+15t^2), t=x^2.
// |err|<1e-4 for |x|<2, ~5e-4 at |x|=3. Division via full-rate MUFU.RCP;
// polynomial runs on the FMA pipe (idle capacity), offloading the
// half-rate MUFU.TANH pipe.
__device__ __forceinline__ float pade_tanh(float x) {
    float t = x * x;
    float n = fmaf(t, t + 105.0f, 945.0f);
    float d = fmaf(t, fmaf(t, 15.0f, 420.0f), 945.0f);
    float r;
    asm("rcp.approx.f32 %0, %1;" : "=f"(r) : "f"(d));
    return x * n * r;
}

// ---------------------------------------------------------------------------
// Kernel 1 (fused projections), 384 blocks x 256 threads.
// ---------------------------------------------------------------------------
__global__ __launch_bounds__(256) void proj_kernel(
    const float* __restrict__ queries, const float* __restrict__ keys,
    const float* __restrict__ wq, const float* __restrict__ wk)
{
    __shared__ __align__(16) float s_buf[16 * 65];
    const int tid = threadIdx.x;
    const int blk = blockIdx.x;

    if (blk < 128) {
        // ---- q projection: rows [row0, row0+16) ----
        const int row0 = blk * 16;
        float w[DIN_];
        #pragma unroll
        for (int d = 0; d < DIN_; d++) w[d] = wq[d * H_ + tid];

        float* s_x = s_buf;                          // [16][64]
        const float* xb = queries + (size_t)row0 * DIN_;
        #pragma unroll
        for (int k = 0; k < 4; k++)
            s_x[tid + k * 256] = xb[tid + k * 256];
        __syncthreads();

        #pragma unroll 4
        for (int r = 0; r < 16; r++) {
            const float4* xr = (const float4*)(s_x + r * DIN_);
            float acc = 0.f;
            #pragma unroll
            for (int d4 = 0; d4 < DIN_ / 4; d4++) {
                float4 xv = xr[d4];
                acc += xv.x * w[d4 * 4 + 0];
                acc += xv.y * w[d4 * 4 + 1];
                acc += xv.z * w[d4 * 4 + 2];
                acc += xv.w * w[d4 * 4 + 3];
            }
            g_q[(size_t)(row0 + r) * H_ + tid] = acc;
        }
    } else {
        // ---- kT projection: batch b, h chunk [h0, h0+16) ----
        const int blk2 = blk - 128;
        const int b  = blk2 >> 4;
        const int h0 = (blk2 & 15) << 4;
        const int t  = tid;

        float x[DIN_];
        const float4* kr = (const float4*)(keys + ((size_t)b * TK_ + t) * DIN_);
        #pragma unroll
        for (int d4 = 0; d4 < DIN_ / 4; d4++) {
            float4 v = kr[d4];
            x[d4 * 4 + 0] = v.x; x[d4 * 4 + 1] = v.y;
            x[d4 * 4 + 2] = v.z; x[d4 * 4 + 3] = v.w;
        }

        float (*s_w)[DIN_ + 1] = (float (*)[DIN_ + 1])s_buf;   // [16][65]
        #pragma unroll
        for (int k = 0; k < 4; k++) {
            int idx = tid + k * 256;
            int hh = idx & 15, d = idx >> 4;
            s_w[hh][d] = wk[d * H_ + h0 + hh];
        }
        __syncthreads();

        float* outb = g_kT + ((size_t)b * H_ + h0) * TK_ + t;
        #pragma unroll 2
        for (int hh = 0; hh < 16; hh++) {
            float acc = 0.f;
            #pragma unroll
            for (int d = 0; d < DIN_; d++) acc += x[d] * s_w[hh][d];
            outb[(size_t)hh * TK_] = acc;
        }
    }
}

// ---------------------------------------------------------------------------
// Kernel 2: fused scores + masked softmax + attn@V.
// CTA = (batch b, 4-query tile); 512 CTAs x 512 threads (16 warps).
//   Phase 1: warp (qg,kq) = query x 64-key quarter; lane owns 2 consecutive
//     keys (coalesced float2 along Tk). Register double-buffer prefetch,
//     depth 2 groups. Within each 4-h group, 2 h-steps use MUFU.TANH and
//     2 use the Pade/RCP path — balancing the half-rate TANH pipe against
//     the idle FMA pipe. Fully-masked quarters skip all work.
//   Softmax: warps 0..3 one row each.
//   Phase 2: threads <256 own output column; loop to ceil(vl/4).
// ---------------------------------------------------------------------------
__global__ __launch_bounds__(512, 2) void attn_kernel(
    const float* __restrict__ values, const int* __restrict__ valid_lens,
    const float* __restrict__ wv, float* __restrict__ out)
{
    const int b  = blockIdx.x >> 5;
    const int i0 = (blockIdx.x & 31) * IT_;
    const int tid  = threadIdx.x;
    const int wid  = tid >> 5;
    const int lane = tid & 31;
    const int qg = wid >> 2;                 // query within tile
    const int kq = wid & 3;                  // 64-key quarter

    __shared__ __align__(16) float s_q[IT_][H_];    // 4 KB
    __shared__ __align__(16) float s_wv[H_];        // 1 KB
    __shared__ __align__(16) float s_sc[IT_][TK_];  // 4 KB

    const int vl = valid_lens[b];
    if (tid < 256) s_wv[tid] = wv[tid];
    #pragma unroll
    for (int k = 0; k < 2; k++) {
        int idx = tid + k * 512;
        s_q[idx >> 8][idx & 255] =
            g_q[((size_t)b * TQ_ + i0 + (idx >> 8)) * H_ + (idx & 255)];
    }
    __syncthreads();

    // ---- Phase 1: scores (register double-buffer, split tanh pipes) ----
    const bool live = (kq * 64 < vl);
    const int kl = kq * 32 + lane;           // float2 index within key row
    float acc0 = 0.f, acc1 = 0.f;

    if (live) {
        constexpr int S = TK_ / 2;           // float2 stride per h-step
        const float2* kp = (const float2*)(g_kT + (size_t)b * H_ * TK_) + kl;

        float2 A0 = kp[0 * S], A1 = kp[1 * S], A2 = kp[2 * S], A3 = kp[3 * S];
        float2 Bb0 = kp[4 * S], Bb1 = kp[5 * S], Bb2 = kp[6 * S], Bb3 = kp[7 * S];
        kp += 8 * S;

        const float4* qv4  = (const float4*)s_q[qg];
        const float4* wvv4 = (const float4*)s_wv;

        #pragma unroll 2
        for (int g = 0; g < H_ / 4; g += 2) {
            // -- group g: consume A (2 TANH h-steps + 2 Pade h-steps), refill A --
            float4 qv  = qv4[g];
            float4 wvv = wvv4[g];
            acc0 = fmaf(wvv.x, fast_tanh(qv.x + A0.x), acc0);
            acc1 = fmaf(wvv.x, fast_tanh(qv.x + A0.y), acc1);
            acc0 = fmaf(wvv.y, fast_tanh(qv.y + A1.x), acc0);
            acc1 = fmaf(wvv.y, fast_tanh(qv.y + A1.y), acc1);
            acc0 = fmaf(wvv.z, pade_tanh(qv.z + A2.x), acc0);
            acc1 = fmaf(wvv.z, pade_tanh(qv.z + A2.y), acc1);
            acc0 = fmaf(wvv.w, pade_tanh(qv.w + A3.x), acc0);
            acc1 = fmaf(wvv.w, pade_tanh(qv.w + A3.y), acc1);
            A0 = kp[0 * S]; A1 = kp[1 * S]; A2 = kp[2 * S]; A3 = kp[3 * S];

            // -- group g+1: consume B (same split), refill B --
            float4 qw  = qv4[g + 1];
            float4 wvw = wvv4[g + 1];
            acc0 = fmaf(wvw.x, fast_tanh(qw.x + Bb0.x), acc0);
            acc1 = fmaf(wvw.x, fast_tanh(qw.x + Bb0.y), acc1);
            acc0 = fmaf(wvw.y, fast_tanh(qw.y + Bb1.x), acc0);
            acc1 = fmaf(wvw.y, fast_tanh(qw.y + Bb1.y), acc1);
            acc0 = fmaf(wvw.z, pade_tanh(qw.z + Bb2.x), acc0);
            acc1 = fmaf(wvw.z, pade_tanh(qw.z + Bb2.y), acc1);
            acc0 = fmaf(wvw.w, pade_tanh(qw.w + Bb3.x), acc0);
            acc1 = fmaf(wvw.w, pade_tanh(qw.w + Bb3.y), acc1);
            Bb0 = kp[4 * S]; Bb1 = kp[5 * S]; Bb2 = kp[6 * S]; Bb3 = kp[7 * S];
            kp += 8 * S;
        }
    }

    {
        const int j0 = kq * 64 + 2 * lane;
        float2 sc;
        sc.x = (live && j0 + 0 < vl) ? acc0 : NEGV;
        sc.y = (live && j0 + 1 < vl) ? acc1 : NEGV;
        ((float2*)s_sc[qg])[kl] = sc;
    }
    __syncthreads();

    // ---- Masked softmax: warps 0..3, one row each ----
    if (tid < IT_ * 32) {
        const int i = wid, l = lane;
        float v[TK_ / 32];
        float m = -3.402823466e38f;
        #pragma unroll
        for (int k = 0; k < TK_ / 32; k++) {
            v[k] = s_sc[i][l + k * 32];
            m = fmaxf(m, v[k]);
        }
        #pragma unroll
        for (int off = 16; off; off >>= 1)
            m = fmaxf(m, __shfl_xor_sync(0xffffffffu, m, off));
        float sum = 0.f;
        #pragma unroll
        for (int k = 0; k < TK_ / 32; k++) {
            v[k] = __expf(v[k] - m);
            sum += v[k];
        }
        #pragma unroll
        for (int off = 16; off; off >>= 1)
            sum += __shfl_xor_sync(0xffffffffu, sum, off);
        const float inv = 1.0f / sum;
        #pragma unroll
        for (int k = 0; k < TK_ / 32; k++)
            s_sc[i][l + k * 32] = v[k] * inv;
    }
    __syncthreads();

    // ---- Phase 2: out = attn @ values, rows < vl only (attn==0 beyond) ----
    if (tid < 256) {
        const int vl_p2 = (vl == 0) ? TK_ : vl;      // vl==0 -> uniform attn
        const int jmax4 = (vl_p2 + 3) >> 2;

        const float* vbase = values + (size_t)b * TK_ * DV_ + tid;
        float oacc[IT_];
        #pragma unroll
        for (int i = 0; i < IT_; i++) oacc[i] = 0.f;

        #pragma unroll 2
        for (int j4 = 0; j4 < jmax4; j4++) {
            float v0 = vbase[(j4 * 4 + 0) * DV_];
            float v1 = vbase[(j4 * 4 + 1) * DV_];
            float v2 = vbase[(j4 * 4 + 2) * DV_];
            float v3 = vbase[(j4 * 4 + 3) * DV_];
            #pragma unroll
            for (int i = 0; i < IT_; i++) {
                float4 a = ((const float4*)s_sc[i])[j4];
                oacc[i] += a.x * v0;
                oacc[i] += a.y * v1;
                oacc[i] += a.z * v2;
                oacc[i] += a.w * v3;
            }
        }
        #pragma unroll
        for (int i = 0; i < IT_; i++)
            out[((size_t)b * TQ_ + i0 + i) * DV_ + tid] = oacc[i];
    }
}

extern "C" void kernel_launch(void* const* d_in, const int* in_sizes, int n_in,
                              void* d_out, int out_size)
{
    const float* queries    = (const float*)d_in[0];
    const float* keys       = (const float*)d_in[1];
    const float* values     = (const float*)d_in[2];
    const int*   valid_lens = (const int*)d_in[3];
    const float* wq         = (const float*)d_in[4];
    const float* wk         = (const float*)d_in[5];
    const float* wv         = (const float*)d_in[6];
    float*       out        = (float*)d_out;

    proj_kernel<<<384, 256>>>(queries, keys, wq, wk);
    attn_kernel<<<(B_ * TQ_) / IT_, 512>>>(values, valid_lens, wv, out);
}

// round 13
// speedup vs baseline: 1.4798x; 1.4798x over previous
#include <cuda_runtime.h>
#include <cuda_bf16.h>
#include <cstdint>

#define B_   16
#define TQ_  128
#define TK_  256
#define DIN_ 64
#define H_   256
#define DV_  256
#define IT_  2           // queries per CTA
#define NEGV (-1000000.0f)

// Scratch (static device arrays: allocation-free). g_kT padded by 8 h-rows so
// the depth-2 prefetch can run past the last row without wrap/guard arithmetic.
__device__ float g_q [B_ * TQ_ * H_];            // [B*Tq, H]
__device__ float g_kT[B_ * H_ * TK_ + 8 * TK_];  // [B, H, Tk] + pad

__device__ __forceinline__ float fast_tanh(float x) {
    float y;
    asm("tanh.approx.f32 %0, %1;" : "=f"(y) : "f"(x));
    return y;
}

// ---------------------------------------------------------------------------
// Kernel 1 (fused projections), 384 blocks x 256 threads.
// ---------------------------------------------------------------------------
__global__ __launch_bounds__(256) void proj_kernel(
    const float* __restrict__ queries, const float* __restrict__ keys,
    const float* __restrict__ wq, const float* __restrict__ wk)
{
    __shared__ __align__(16) float s_buf[16 * 65];
    const int tid = threadIdx.x;
    const int blk = blockIdx.x;

    if (blk < 128) {
        // ---- q projection: rows [row0, row0+16) ----
        const int row0 = blk * 16;
        float w[DIN_];
        #pragma unroll
        for (int d = 0; d < DIN_; d++) w[d] = wq[d * H_ + tid];

        float* s_x = s_buf;                          // [16][64]
        const float* xb = queries + (size_t)row0 * DIN_;
        #pragma unroll
        for (int k = 0; k < 4; k++)
            s_x[tid + k * 256] = xb[tid + k * 256];
        __syncthreads();

        #pragma unroll 4
        for (int r = 0; r < 16; r++) {
            const float4* xr = (const float4*)(s_x + r * DIN_);
            float acc = 0.f;
            #pragma unroll
            for (int d4 = 0; d4 < DIN_ / 4; d4++) {
                float4 xv = xr[d4];
                acc += xv.x * w[d4 * 4 + 0];
                acc += xv.y * w[d4 * 4 + 1];
                acc += xv.z * w[d4 * 4 + 2];
                acc += xv.w * w[d4 * 4 + 3];
            }
            g_q[(size_t)(row0 + r) * H_ + tid] = acc;
        }
    } else {
        // ---- kT projection: batch b, h chunk [h0, h0+16) ----
        const int blk2 = blk - 128;
        const int b  = blk2 >> 4;
        const int h0 = (blk2 & 15) << 4;
        const int t  = tid;

        float x[DIN_];
        const float4* kr = (const float4*)(keys + ((size_t)b * TK_ + t) * DIN_);
        #pragma unroll
        for (int d4 = 0; d4 < DIN_ / 4; d4++) {
            float4 v = kr[d4];
            x[d4 * 4 + 0] = v.x; x[d4 * 4 + 1] = v.y;
            x[d4 * 4 + 2] = v.z; x[d4 * 4 + 3] = v.w;
        }

        float (*s_w)[DIN_ + 1] = (float (*)[DIN_ + 1])s_buf;   // [16][65]
        #pragma unroll
        for (int k = 0; k < 4; k++) {
            int idx = tid + k * 256;
            int hh = idx & 15, d = idx >> 4;
            s_w[hh][d] = wk[d * H_ + h0 + hh];
        }
        __syncthreads();

        float* outb = g_kT + ((size_t)b * H_ + h0) * TK_ + t;
        #pragma unroll 2
        for (int hh = 0; hh < 16; hh++) {
            float acc = 0.f;
            #pragma unroll
            for (int d = 0; d < DIN_; d++) acc += x[d] * s_w[hh][d];
            outb[(size_t)hh * TK_] = acc;
        }
    }
}

// ---------------------------------------------------------------------------
// Kernel 2: fused scores + masked softmax + attn@V.
// CTA = (batch b, 2-query tile); 1024 CTAs x 512 threads (16 warps).
//   Phase 1: warp w -> (qg = w>>3, kq = (w>>1)&3, hh = w&1): query x 64-key
//     quarter x 128-h half. Lane owns 2 consecutive keys (coalesced float2
//     along Tk). Register double-buffer prefetch depth 2; per-warp critical
//     path is HALF of the full-H variant. Fully-masked quarters skip compute
//     and store zero partials.
//   Combine+softmax: warps 0..1, one row each (sums the two h-half partials,
//     applies mask).
//   Phase 2: threads <256 own output column; loop to ceil(vl/4).
// ---------------------------------------------------------------------------
__global__ __launch_bounds__(512, 2) void attn_kernel(
    const float* __restrict__ values, const int* __restrict__ valid_lens,
    const float* __restrict__ wv, float* __restrict__ out)
{
    const int b  = blockIdx.x >> 6;          // 64 q-tiles per batch
    const int i0 = (blockIdx.x & 63) * IT_;
    const int tid  = threadIdx.x;
    const int wid  = tid >> 5;
    const int lane = tid & 31;
    const int qg = wid >> 3;                 // query within tile (0..1)
    const int kq = (wid >> 1) & 3;           // 64-key quarter
    const int hh = wid & 1;                  // h half (0..1)

    __shared__ __align__(16) float s_q[IT_][H_];        // 2 KB
    __shared__ __align__(16) float s_wv[H_];            // 1 KB
    __shared__ __align__(16) float s_p[IT_][2][TK_];    // 4 KB partials
    __shared__ __align__(16) float s_sc[IT_][TK_];      // 2 KB

    const int vl = valid_lens[b];
    if (tid < 256) s_wv[tid] = wv[tid];
    if (tid < IT_ * H_)
        s_q[tid >> 8][tid & 255] =
            g_q[((size_t)b * TQ_ + i0 + (tid >> 8)) * H_ + (tid & 255)];
    __syncthreads();

    // ---- Phase 1: partial scores over this warp's 128-h half ----
    const bool live = (kq * 64 < vl);
    const int kl = kq * 32 + lane;           // float2 index within key row
    float acc0 = 0.f, acc1 = 0.f;

    if (live) {
        constexpr int S = TK_ / 2;           // float2 stride per h-step
        const float2* kp =
            (const float2*)(g_kT + ((size_t)b * H_ + hh * (H_ / 2)) * TK_) + kl;

        float2 A0 = kp[0 * S], A1 = kp[1 * S], A2 = kp[2 * S], A3 = kp[3 * S];
        float2 Bb0 = kp[4 * S], Bb1 = kp[5 * S], Bb2 = kp[6 * S], Bb3 = kp[7 * S];
        kp += 8 * S;

        const float4* qv4  = (const float4*)s_q[qg] + hh * (H_ / 8);
        const float4* wvv4 = (const float4*)s_wv    + hh * (H_ / 8);

        #pragma unroll 2
        for (int g = 0; g < H_ / 8; g += 2) {
            // -- group g: consume A, refill A --
            float4 qv  = qv4[g];
            float4 wvv = wvv4[g];
            acc0 = fmaf(wvv.x, fast_tanh(qv.x + A0.x), acc0);
            acc1 = fmaf(wvv.x, fast_tanh(qv.x + A0.y), acc1);
            acc0 = fmaf(wvv.y, fast_tanh(qv.y + A1.x), acc0);
            acc1 = fmaf(wvv.y, fast_tanh(qv.y + A1.y), acc1);
            acc0 = fmaf(wvv.z, fast_tanh(qv.z + A2.x), acc0);
            acc1 = fmaf(wvv.z, fast_tanh(qv.z + A2.y), acc1);
            acc0 = fmaf(wvv.w, fast_tanh(qv.w + A3.x), acc0);
            acc1 = fmaf(wvv.w, fast_tanh(qv.w + A3.y), acc1);
            A0 = kp[0 * S]; A1 = kp[1 * S]; A2 = kp[2 * S]; A3 = kp[3 * S];

            // -- group g+1: consume B, refill B --
            float4 qw  = qv4[g + 1];
            float4 wvw = wvv4[g + 1];
            acc0 = fmaf(wvw.x, fast_tanh(qw.x + Bb0.x), acc0);
            acc1 = fmaf(wvw.x, fast_tanh(qw.x + Bb0.y), acc1);
            acc0 = fmaf(wvw.y, fast_tanh(qw.y + Bb1.x), acc0);
            acc1 = fmaf(wvw.y, fast_tanh(qw.y + Bb1.y), acc1);
            acc0 = fmaf(wvw.z, fast_tanh(qw.z + Bb2.x), acc0);
            acc1 = fmaf(wvw.z, fast_tanh(qw.z + Bb2.y), acc1);
            acc0 = fmaf(wvw.w, fast_tanh(qw.w + Bb3.x), acc0);
            acc1 = fmaf(wvw.w, fast_tanh(qw.w + Bb3.y), acc1);
            Bb0 = kp[4 * S]; Bb1 = kp[5 * S]; Bb2 = kp[6 * S]; Bb3 = kp[7 * S];
            kp += 8 * S;
        }
    }
    // All warps store partials (dead warps contribute zeros).
    ((float2*)s_p[qg][hh])[kl] = make_float2(acc0, acc1);
    __syncthreads();

    // ---- Combine partials + masked softmax: warps 0..1, one row each ----
    if (tid < IT_ * 32) {
        const int i = wid, l = lane;
        float v[TK_ / 32];
        float m = -3.402823466e38f;
        #pragma unroll
        for (int k = 0; k < TK_ / 32; k++) {
            int j = l + k * 32;
            float p = s_p[i][0][j] + s_p[i][1][j];
            v[k] = (j < vl) ? p : NEGV;
            m = fmaxf(m, v[k]);
        }
        #pragma unroll
        for (int off = 16; off; off >>= 1)
            m = fmaxf(m, __shfl_xor_sync(0xffffffffu, m, off));
        float sum = 0.f;
        #pragma unroll
        for (int k = 0; k < TK_ / 32; k++) {
            v[k] = __expf(v[k] - m);
            sum += v[k];
        }
        #pragma unroll
        for (int off = 16; off; off >>= 1)
            sum += __shfl_xor_sync(0xffffffffu, sum, off);
        const float inv = 1.0f / sum;
        #pragma unroll
        for (int k = 0; k < TK_ / 32; k++)
            s_sc[i][l + k * 32] = v[k] * inv;
    }
    __syncthreads();

    // ---- Phase 2: out = attn @ values, rows < vl only (attn==0 beyond) ----
    if (tid < 256) {
        const int vl_p2 = (vl == 0) ? TK_ : vl;      // vl==0 -> uniform attn
        const int jmax4 = (vl_p2 + 3) >> 2;

        const float* vbase = values + (size_t)b * TK_ * DV_ + tid;
        float oacc[IT_];
        #pragma unroll
        for (int i = 0; i < IT_; i++) oacc[i] = 0.f;

        #pragma unroll 2
        for (int j4 = 0; j4 < jmax4; j4++) {
            float v0 = vbase[(j4 * 4 + 0) * DV_];
            float v1 = vbase[(j4 * 4 + 1) * DV_];
            float v2 = vbase[(j4 * 4 + 2) * DV_];
            float v3 = vbase[(j4 * 4 + 3) * DV_];
            #pragma unroll
            for (int i = 0; i < IT_; i++) {
                float4 a = ((const float4*)s_sc[i])[j4];
                oacc[i] += a.x * v0;
                oacc[i] += a.y * v1;
                oacc[i] += a.z * v2;
                oacc[i] += a.w * v3;
            }
        }
        #pragma unroll
        for (int i = 0; i < IT_; i++)
            out[((size_t)b * TQ_ + i0 + i) * DV_ + tid] = oacc[i];
    }
}

extern "C" void kernel_launch(void* const* d_in, const int* in_sizes, int n_in,
                              void* d_out, int out_size)
{
    const float* queries    = (const float*)d_in[0];
    const float* keys       = (const float*)d_in[1];
    const float* values     = (const float*)d_in[2];
    const int*   valid_lens = (const int*)d_in[3];
    const float* wq         = (const float*)d_in[4];
    const float* wk         = (const float*)d_in[5];
    const float* wv         = (const float*)d_in[6];
    float*       out        = (float*)d_out;

    proj_kernel<<<384, 256>>>(queries, keys, wq, wk);
    attn_kernel<<<(B_ * TQ_) / IT_, 512>>>(values, valid_lens, wv, out);
}